// round 3
// baseline (speedup 1.0000x reference)
#include <cuda_runtime.h>
#include <cuda_bf16.h>
#include <cstdint>

// out[n, d] = input[n, d] * W[d];  N=16384, D=4096, fp32.
// HBM-bound streaming: 256MB in + 256MB out.
//
// Layout: each thread owns ONE fixed float4-column and processes R rows.
// - W loaded once per thread into a register (no per-element W traffic).
// - R=8 front-batched LDG.128 per iteration -> MLP=8, hides DRAM latency.
// - Coalescing: warp covers 512B contiguous per row; 4 blocks tile the
//   full 16KB row contiguously.

static constexpr int N_ROWS = 16384;
static constexpr int D4 = 4096 / 4;           // 1024 float4 per row
static constexpr int R = 8;                   // rows per thread
static constexpr int THREADS = 256;
static constexpr int BLOCKS_PER_ROWGROUP = D4 / THREADS;  // 4
static constexpr int ROWGROUPS = N_ROWS / R;              // 2048
static constexpr int GRID = ROWGROUPS * BLOCKS_PER_ROWGROUP; // 8192

__global__ void __launch_bounds__(THREADS) diag_scale_colmajor_kernel(
    const float4* __restrict__ in,
    const float4* __restrict__ w,
    float4* __restrict__ out)
{
    unsigned col = (blockIdx.x & (BLOCKS_PER_ROWGROUP - 1)) * THREADS + threadIdx.x;
    unsigned row0 = (blockIdx.x >> 2) * R;    // BLOCKS_PER_ROWGROUP == 4

    float4 wv = __ldg(&w[col]);

    unsigned base = row0 * D4 + col;

    float4 a[R];
#pragma unroll
    for (int i = 0; i < R; i++)
        a[i] = in[base + i * D4];

#pragma unroll
    for (int i = 0; i < R; i++) {
        float4 r;
        r.x = a[i].x * wv.x;
        r.y = a[i].y * wv.y;
        r.z = a[i].z * wv.z;
        r.w = a[i].w * wv.w;
        out[base + i * D4] = r;
    }
}

extern "C" void kernel_launch(void* const* d_in, const int* in_sizes, int n_in,
                              void* d_out, int out_size) {
    const float4* in = (const float4*)d_in[0];
    const float4* w  = (const float4*)d_in[1];
    float4* out = (float4*)d_out;
    diag_scale_colmajor_kernel<<<GRID, THREADS>>>(in, w, out);
}

// round 4
// speedup vs baseline: 1.0078x; 1.0078x over previous
#include <cuda_runtime.h>
#include <cuda_bf16.h>
#include <cstdint>

// out[n, d] = input[n, d] * W[d];  N=16384, D=4096, fp32.
// Pure stream: 256MB read-once + 256MB write-once. DRAM-bound.
//
// R3 changes vs R2:
//  - __ldcs / __stcs streaming hints: data is never reused, so mark both
//    streams evict-first to stop L2 churning on 512MB of transient lines.
//  - R=16 rows/thread: MLP 16 front-batched LDG.128, fewer blocks.
// Layout unchanged: thread owns one float4-column; warp reads 512B/row
// contiguous; 4 blocks tile the full 16KB row.

static constexpr int N_ROWS = 16384;
static constexpr int D4 = 4096 / 4;            // 1024 float4 per row
static constexpr int R = 16;                   // rows per thread
static constexpr int THREADS = 256;
static constexpr int BLOCKS_PER_ROWGROUP = D4 / THREADS;   // 4
static constexpr int ROWGROUPS = N_ROWS / R;               // 1024
static constexpr int GRID = ROWGROUPS * BLOCKS_PER_ROWGROUP; // 4096

__global__ void __launch_bounds__(THREADS) diag_scale_stream_kernel(
    const float4* __restrict__ in,
    const float4* __restrict__ w,
    float4* __restrict__ out)
{
    unsigned col  = (blockIdx.x & (BLOCKS_PER_ROWGROUP - 1)) * THREADS + threadIdx.x;
    unsigned row0 = (blockIdx.x >> 2) * R;     // BLOCKS_PER_ROWGROUP == 4

    float4 wv = __ldg(&w[col]);                // W is hot/reused: keep cached

    unsigned base = row0 * D4 + col;

    float4 a[R];
#pragma unroll
    for (int i = 0; i < R; i++)
        a[i] = __ldcs(&in[base + i * D4]);     // evict-first load

#pragma unroll
    for (int i = 0; i < R; i++) {
        float4 r;
        r.x = a[i].x * wv.x;
        r.y = a[i].y * wv.y;
        r.z = a[i].z * wv.z;
        r.w = a[i].w * wv.w;
        __stcs(&out[base + i * D4], r);        // streaming store
    }
}

extern "C" void kernel_launch(void* const* d_in, const int* in_sizes, int n_in,
                              void* d_out, int out_size) {
    const float4* in = (const float4*)d_in[0];
    const float4* w  = (const float4*)d_in[1];
    float4* out = (float4*)d_out;
    diag_scale_stream_kernel<<<GRID, THREADS>>>(in, w, out);
}

// round 5
// speedup vs baseline: 1.0082x; 1.0004x over previous
#include <cuda_runtime.h>
#include <cuda_bf16.h>
#include <cstdint>

// out[n, d] = input[n, d] * W[d];  N=16384, D=4096, fp32.
// Pure stream: 256MB read-once + 256MB write-once. DRAM-bound at ~6.4TB/s.
//
// R4 changes vs R3:
//  - CTA owns a fully CONTIGUOUS 64KB region: 512 threads cover half a row
//    (8KB) and iterate 8 row-steps -> long contiguous read bursts then write
//    bursts per CTA (DRAM page locality, fewer rd/wr turnarounds).
//  - R=8 (regs ~40) restores occupancy (R3 was 30%) for more chipwide MLP.
//  - Keep __ldcs/__stcs streaming hints and per-thread W register.

static constexpr int N_ROWS = 16384;
static constexpr int D4 = 4096 / 4;              // 1024 float4 per row
static constexpr int THREADS = 512;
static constexpr int HALF = D4 / THREADS;        // 2 halves per row
static constexpr int R = 8;                      // row-steps per CTA
// Each CTA: fixed half (0/1), rows [g*R, g*R+8). Region is contiguous because
// consecutive "virtual rows" of width 512 float4 tile memory linearly.
static constexpr int GRID = (N_ROWS * HALF) / R; // 4096

__global__ void __launch_bounds__(THREADS) diag_scale_burst_kernel(
    const float4* __restrict__ in,
    const float4* __restrict__ w,
    float4* __restrict__ out)
{
    // Treat memory as rows of 512 float4 (half-rows). Virtual row v maps to
    // real (row = v>>1, half = v&1). CTA b owns virtual rows [b*R, b*R+R),
    // i.e. a contiguous 64KB span starting at b*R*512 float4s.
    unsigned vbase = blockIdx.x * (unsigned)R;          // first virtual row
    unsigned col   = ((vbase & 1u) ? THREADS : 0u) + threadIdx.x; // D4-column of first vrow
    // Since R is even and vbase = b*8 is even, (vbase&1)==0 always:
    col = threadIdx.x + ((vbase & 1u) * THREADS);

    unsigned base = vbase * THREADS + threadIdx.x;      // linear float4 index

    // W for this thread's column; within the 8 virtual rows the real column
    // alternates only if R were odd — here vbase even & each vrow advances
    // the half: vrow v has real col = (v&1)*512 + tid. Rows alternate halves!
    // So precompute both W values.
    float4 w_even = __ldg(&w[threadIdx.x]);             // half 0
    float4 w_odd  = __ldg(&w[THREADS + threadIdx.x]);   // half 1

    float4 a[R];
#pragma unroll
    for (int i = 0; i < R; i++)
        a[i] = __ldcs(&in[base + (unsigned)i * THREADS]);

#pragma unroll
    for (int i = 0; i < R; i++) {
        // virtual row vbase+i: half = (vbase+i)&1 = i&1 (vbase even)
        float4 wv = (i & 1) ? w_odd : w_even;
        float4 r;
        r.x = a[i].x * wv.x;
        r.y = a[i].y * wv.y;
        r.z = a[i].z * wv.z;
        r.w = a[i].w * wv.w;
        __stcs(&out[base + (unsigned)i * THREADS], r);
    }
}

extern "C" void kernel_launch(void* const* d_in, const int* in_sizes, int n_in,
                              void* d_out, int out_size) {
    const float4* in = (const float4*)d_in[0];
    const float4* w  = (const float4*)d_in[1];
    float4* out = (float4*)d_out;
    diag_scale_burst_kernel<<<GRID, THREADS>>>(in, w, out);
}